// round 8
// baseline (speedup 1.0000x reference)
#include <cuda_runtime.h>
#include <cuda_bf16.h>

typedef unsigned int u32;

#define BB 64
#define TT 1024
#define DD 128
#define QT 32                  // q rows per CTA
#define KT 64                  // k-seq tile
#define NTHREADS 512
#define SSTRIDE 1032
#define SCALE 0.08838834764831845f
#define LOG2E 1.4426950408889634f
// scores live in log2 domain; masked fill = huge negative (exp2 -> 0)
#define MASK_FILL_L2 (-6.0e9f)

// ---- smem layout (bytes) ----
#define SM_SS    0                          // 32 x 1032 f32 scores (132096)
#define SM_KV    132096                     // 2 stages x {hi 16KB, lo 16KB}
#define SM_QP    (SM_KV + 2*32768)          // phase1: Q image hi/lo (8KB+8KB)
                                            // phase3: 2 P stages x {hi 4KB, lo 4KB}
#define SM_TOTAL (SM_QP + 16384)            // 214016

// 256B-row tiles: 16B unit `unit` of row `row`
#define SWZ_UNIT(row, unit) ((u32)(row) * 256u + (((u32)(unit) ^ ((u32)(row) & 7u)) << 4))
// 128B-row tiles (P): 8 units per row
#define SWZP_UNIT(row, unit) ((u32)(row) * 128u + (((u32)(unit) ^ ((u32)(row) & 7u)) << 4))

// ---- precomputed bf16 hi/lo operand images (swizzled smem-identical tiles) ----
__device__ __align__(16) unsigned char g_QHI[1 << 24];
__device__ __align__(16) unsigned char g_QLO[1 << 24];
__device__ __align__(16) unsigned char g_KHI[1 << 24];
__device__ __align__(16) unsigned char g_KLO[1 << 24];
__device__ __align__(16) unsigned char g_VHI[1 << 24];
__device__ __align__(16) unsigned char g_VLO[1 << 24];

// ================= PTX helpers =================
__device__ __forceinline__ u32 smem_u32(const void* p) {
    u32 a;
    asm("{ .reg .u64 t; cvta.to.shared.u64 t, %1; cvt.u32.u64 %0, t; }" : "=r"(a) : "l"(p));
    return a;
}
__device__ __forceinline__ void cp16(u32 dst, const void* src) {
    asm volatile("cp.async.cg.shared.global [%0], [%1], 16;" :: "r"(dst), "l"(src));
}
#define CP_COMMIT() asm volatile("cp.async.commit_group;" ::: "memory")
#define CP_WAIT_ALL() asm volatile("cp.async.wait_group 0;" ::: "memory")

__device__ __forceinline__ void ldm_x4(u32* r, u32 addr) {
    asm volatile("ldmatrix.sync.aligned.m8n8.x4.shared.b16 {%0,%1,%2,%3}, [%4];"
                 : "=r"(r[0]), "=r"(r[1]), "=r"(r[2]), "=r"(r[3]) : "r"(addr));
}
__device__ __forceinline__ void ldm_x4t(u32* r, u32 addr) {
    asm volatile("ldmatrix.sync.aligned.m8n8.x4.trans.shared.b16 {%0,%1,%2,%3}, [%4];"
                 : "=r"(r[0]), "=r"(r[1]), "=r"(r[2]), "=r"(r[3]) : "r"(addr));
}
__device__ __forceinline__ void mma16816(float* c, const u32* a, const u32* b) {
    asm volatile(
        "mma.sync.aligned.m16n8k16.row.col.f32.bf16.bf16.f32 "
        "{%0,%1,%2,%3}, {%4,%5,%6,%7}, {%8,%9}, {%0,%1,%2,%3};"
        : "+f"(c[0]), "+f"(c[1]), "+f"(c[2]), "+f"(c[3])
        : "r"(a[0]), "r"(a[1]), "r"(a[2]), "r"(a[3]), "r"(b[0]), "r"(b[1]));
}
__device__ __forceinline__ void cvt_split2(float x0, float x1, u32& hi, u32& lo) {
    __nv_bfloat16 h0 = __float2bfloat16(x0);
    __nv_bfloat16 h1 = __float2bfloat16(x1);
    __nv_bfloat16 l0 = __float2bfloat16(x0 - __bfloat162float(h0));
    __nv_bfloat16 l1 = __float2bfloat16(x1 - __bfloat162float(h1));
    __nv_bfloat162 H(h0, h1), L(l0, l1);
    hi = *reinterpret_cast<u32*>(&H);
    lo = *reinterpret_cast<u32*>(&L);
}

// ---- exp2 two ways: MUFU pipe and FFMA-pipe polynomial ----
__device__ __forceinline__ float exp2_mufu(float v) {
    float r;
    asm("ex2.approx.f32 %0, %1;" : "=f"(r) : "f"(v));
    return r;
}
__device__ __forceinline__ float exp2_poly(float v) {
    v = fmaxf(v, -126.0f);
    float f = v + 12582912.0f;                 // round-to-nearest integer (magic)
    int n = __float_as_int(f) - 0x4B400000;    // integer part
    float r = v - (f - 12582912.0f);           // r in [-0.5, 0.5]
    float p = fmaf(r, 0.0013333558f, 0.009618129f);
    p = fmaf(p, r, 0.05550411f);
    p = fmaf(p, r, 0.2402265f);
    p = fmaf(p, r, 0.6931472f);
    p = fmaf(p, r, 1.0f);
    return __int_as_float(__float_as_int(p) + (n << 23));
}

// ---------------- mask dtype probe + mode ----------------
__device__ int g_mask_mode;   // 0=u8, 1=i32, 2=f32

__device__ __forceinline__ bool mask_at(const void* __restrict__ m, size_t idx, int mode)
{
    if (mode == 0) return ((const unsigned char*)m)[idx] != 0;
    if (mode == 1) return ((const int*)m)[idx] != 0;
    return ((const float*)m)[idx] != 0.0f;
}

// ---------------- prep: f32 -> bf16 hi/lo swizzled tile images (+ mask probe) ----------------
__global__ __launch_bounds__(512)
void prep_kernel(const float* __restrict__ query,
                 const float* __restrict__ key,
                 const float* __restrict__ value,
                 const unsigned char* __restrict__ mask)
{
    if (blockIdx.x == 6144) {   // probe block (warp 0 only)
        if (threadIdx.x >= 32) return;
        const int lane = threadIdx.x;
        const float* mf = (const float*)mask;
        bool f01 = true;
        for (int i = lane; i < 1024; i += 32) {
            float f = mf[i];
            if (f != 0.0f && f != 1.0f) f01 = false;
        }
        if (__all_sync(0xffffffffu, f01)) {
            if (lane == 0) g_mask_mode = 2;
            return;
        }
        u32 any_high = 0;
        for (int i = lane * 4; i < 4096; i += 128)
            any_high |= (mask[i + 1] | mask[i + 2] | mask[i + 3]);
        int any = __any_sync(0xffffffffu, any_high != 0);
        if (lane == 0) g_mask_mode = any ? 0 : 1;
        return;
    }

    int idx = blockIdx.x * blockDim.x + threadIdx.x;   // 3 * 1048576 total
    int tensor = idx >> 20;
    int u = idx & 1048575;           // b(6) | seq(10) | unit(4)
    int unit = u & 15;
    int seq = (u >> 4) & 1023;
    int b = u >> 14;

    const float* src;
    unsigned char *dhi, *dlo;
    float scale = 1.0f;
    size_t img;
    int r;
    if (tensor == 0) {
        src = query; dhi = g_QHI; dlo = g_QLO; scale = SCALE * LOG2E;  // log2 domain
        img = (size_t)(b * 32 + (seq >> 5)) << 13; r = seq & 31;
    } else if (tensor == 1) {
        src = key; dhi = g_KHI; dlo = g_KLO;
        img = (size_t)(b * 16 + (seq >> 6)) << 14; r = seq & 63;
    } else {
        src = value; dhi = g_VHI; dlo = g_VLO;
        img = (size_t)(b * 16 + (seq >> 6)) << 14; r = seq & 63;
    }
    const float4* s4 = (const float4*)(src + ((size_t)b * TT + seq) * DD + unit * 8);
    float4 x0 = s4[0], x1 = s4[1];
    uint4 H, L;
    cvt_split2(x0.x * scale, x0.y * scale, H.x, L.x);
    cvt_split2(x0.z * scale, x0.w * scale, H.y, L.y);
    cvt_split2(x1.x * scale, x1.y * scale, H.z, L.z);
    cvt_split2(x1.z * scale, x1.w * scale, H.w, L.w);
    u32 off = (u32)r * 256u + (((u32)(unit ^ (r & 7))) << 4);
    *(uint4*)(dhi + img + off) = H;
    *(uint4*)(dlo + img + off) = L;
}

// ---------------- tile copy helpers ----------------
__device__ __forceinline__ void copy_kv_tile(u32 dst, const unsigned char* ghi,
                                             const unsigned char* glo, size_t base, int tid)
{
    #pragma unroll
    for (int i = 0; i < 2; ++i) {
        int c = tid + i * 512;
        cp16(dst + c * 16, ghi + base + (size_t)c * 16);
        cp16(dst + 16384 + c * 16, glo + base + (size_t)c * 16);
    }
}

// ================= fused attention =================
__global__ __launch_bounds__(NTHREADS, 1)
void mh_attn_mma5_kernel(const void* __restrict__ mask,
                         const float* __restrict__ qmask,
                         float* __restrict__ out_res,
                         float* __restrict__ out_attn)
{
    extern __shared__ char smem[];
    float* sS = (float*)smem;
    const u32 sb = smem_u32(smem);

    const int b    = blockIdx.x >> 5;
    const int q0   = (blockIdx.x & 31) * QT;
    const int tid  = threadIdx.x;
    const int wid  = tid >> 5;
    const int lane = tid & 31;
    const int grp  = lane >> 3;
    const int sub  = lane & 7;
    const int g    = lane >> 2;
    const int t    = lane & 3;
    const int wm   = wid & 1;
    const int wn   = wid >> 1;      // 0..7
    const int m0   = wm * 16;

    // ---- preload Q image + K tile 0 ----
    {
        size_t qimg = (size_t)(b * 32 + (q0 >> 5)) << 13;
        cp16(sb + SM_QP + tid * 16, g_QHI + qimg + (size_t)tid * 16);
        cp16(sb + SM_QP + 8192 + tid * 16, g_QLO + qimg + (size_t)tid * 16);
        copy_kv_tile(sb + SM_KV, g_KHI, g_KLO, (size_t)(b * 16) << 14, tid);
        CP_COMMIT();
        CP_WAIT_ALL();
    }
    __syncthreads();

    // ---- cache Q fragments (m16 x k128, hi+lo) ----
    u32 qhi[8][4], qlo[8][4];
    {
        int rowA = m0 + sub + ((grp & 1) << 3);
        #pragma unroll
        for (int ks = 0; ks < 8; ++ks) {
            u32 off = SWZ_UNIT(rowA, 2 * ks + (grp >> 1));
            ldm_x4(qhi[ks], sb + SM_QP + off);
            ldm_x4(qlo[ks], sb + SM_QP + 8192 + off);
        }
    }

    // =========== Phase 1: S' = (Q*scale*log2e) @ K^T -> sS ===========
    {
        const int rowB   = wn * 8 + sub;
        const u32 hilo   = (grp >> 1) ? 16384u : 0u;
        for (int kt = 0; kt < TT / KT; ++kt) {
            if (kt < 15) {
                copy_kv_tile(sb + SM_KV + ((kt + 1) & 1) * 32768,
                             g_KHI, g_KLO, (size_t)(b * 16 + kt + 1) << 14, tid);
                CP_COMMIT();
            }
            const u32 stage = sb + SM_KV + (kt & 1) * 32768 + hilo;
            float ahh[4] = {0.f,0.f,0.f,0.f};
            float ahl[4] = {0.f,0.f,0.f,0.f};
            float alh[4] = {0.f,0.f,0.f,0.f};
            #pragma unroll
            for (int ks = 0; ks < 8; ++ks) {
                u32 bb[4];   // bb[0..1]=bhi, bb[2..3]=blo (lane-mixed tiles)
                ldm_x4(bb, stage + SWZ_UNIT(rowB, 2 * ks + (grp & 1)));
                mma16816(ahh, qhi[ks], bb);
                mma16816(ahl, qhi[ks], bb + 2);
                mma16816(alh, qlo[ks], bb);
            }
            int col = kt * KT + wn * 8 + 2 * t;
            *(float2*)&sS[(m0 + g) * SSTRIDE + col] =
                make_float2(ahh[0] + ahl[0] + alh[0], ahh[1] + ahl[1] + alh[1]);
            *(float2*)&sS[(m0 + g + 8) * SSTRIDE + col] =
                make_float2(ahh[2] + ahl[2] + alh[2], ahh[3] + ahl[3] + alh[3]);
            if (kt < 15) CP_WAIT_ALL();
            __syncthreads();
        }
    }

    // =========== Phase 2: mask + softmax (exp2, dual-pipe) + query_mask ===========
    {
        const int mmode = g_mask_mode;
        float* attn_g = out_attn + ((size_t)b * TT + q0) * TT;
        for (int r = wid; r < QT; r += 16) {
            float* row = sS + r * SSTRIDE;
            const size_t mrow = (size_t)b * TT * TT + (size_t)(q0 + r) * TT;
            float mx = -3.402823466e38f;
            for (int i = lane; i < TT; i += 32) {
                float s = row[i];
                if (mask_at(mask, mrow + i, mmode)) s = MASK_FILL_L2;
                row[i] = s;
                mx = fmaxf(mx, s);
            }
            #pragma unroll
            for (int o = 16; o; o >>= 1) mx = fmaxf(mx, __shfl_xor_sync(0xffffffffu, mx, o));

            // exp2 pass: 3/5 MUFU, 2/5 FFMA-poly (concurrent pipes)
            float sum0 = 0.f, sum1 = 0.f;
            #pragma unroll
            for (int j = 0; j < 32; ++j) {
                int i = lane + 32 * j;
                float v = row[i] - mx;
                float e = ((j % 5) < 3) ? exp2_mufu(v) : exp2_poly(v);
                if (j & 1) sum1 += e; else sum0 += e;
                row[i] = e;
            }
            float sum = sum0 + sum1;
            #pragma unroll
            for (int o = 16; o; o >>= 1) sum += __shfl_xor_sync(0xffffffffu, sum, o);
            float inv = qmask[(size_t)b * TT + q0 + r] / sum;
            for (int i = lane; i < TT; i += 32) {
                float v = row[i] * inv;
                row[i] = v;
                attn_g[(size_t)r * TT + i] = v;
            }
        }
    }
    __syncthreads();

    // =========== Phase 3: result = P @ V ===========
    float rhh[2][4] = {{0.f,0.f,0.f,0.f},{0.f,0.f,0.f,0.f}};
    float rhl[2][4] = {{0.f,0.f,0.f,0.f},{0.f,0.f,0.f,0.f}};
    float rlh[2][4] = {{0.f,0.f,0.f,0.f},{0.f,0.f,0.f,0.f}};
    {
        auto convert_P = [&](int kt) {
            char* ps = smem + SM_QP + (kt & 1) * 8192;
            #pragma unroll
            for (int i = 0; i < 2; ++i) {
                int j = tid + i * 512;
                int r = j >> 5, c2 = j & 31;
                float2 p2 = *(const float2*)&sS[r * SSTRIDE + kt * KT + 2 * c2];
                u32 hi, lo;
                cvt_split2(p2.x, p2.y, hi, lo);
                u32 off = SWZP_UNIT(r, c2 >> 2) + ((c2 & 3) << 2);
                *(u32*)(ps + off) = hi;
                *(u32*)(ps + 4096 + off) = lo;
            }
        };

        convert_P(0);
        copy_kv_tile(sb + SM_KV, g_VHI, g_VLO, (size_t)(b * 16) << 14, tid);
        CP_COMMIT();
        CP_WAIT_ALL();
        __syncthreads();

        const int rowA  = m0 + sub + ((grp & 1) << 3);
        const int rowB0 = sub + ((grp & 1) << 3);
        const int unitB = 2 * wn + (grp >> 1);

        for (int kt = 0; kt < TT / KT; ++kt) {
            if (kt < 15) {
                copy_kv_tile(sb + SM_KV + ((kt + 1) & 1) * 32768,
                             g_VHI, g_VLO, (size_t)(b * 16 + kt + 1) << 14, tid);
                CP_COMMIT();
            }
            const u32 stV = sb + SM_KV + (kt & 1) * 32768;
            const u32 stP = sb + SM_QP + (kt & 1) * 8192;
            #pragma unroll
            for (int ks = 0; ks < 4; ++ks) {
                u32 offA = SWZP_UNIT(rowA, 2 * ks + (grp >> 1));
                u32 ah[4], al[4];
                ldm_x4(ah, stP + offA);
                ldm_x4(al, stP + 4096 + offA);
                u32 offB = SWZ_UNIT(ks * 16 + rowB0, unitB);
                u32 bh[4], bl[4];
                ldm_x4t(bh, stV + offB);
                ldm_x4t(bl, stV + 16384 + offB);
                #pragma unroll
                for (int tile = 0; tile < 2; ++tile) {
                    mma16816(rhh[tile], ah, bh + 2 * tile);
                    mma16816(rhl[tile], ah, bl + 2 * tile);
                    mma16816(rlh[tile], al, bh + 2 * tile);
                }
            }
            if (kt < 15) {
                convert_P(kt + 1);
                CP_WAIT_ALL();
                __syncthreads();
            }
        }
    }

    // ---- result epilogue ----
    #pragma unroll
    for (int tile = 0; tile < 2; ++tile) {
        int col = wn * 16 + tile * 8 + 2 * t;
        int row = q0 + m0 + g;
        *(float2*)&out_res[((size_t)b * TT + row) * DD + col] =
            make_float2(rhh[tile][0] + rhl[tile][0] + rlh[tile][0],
                        rhh[tile][1] + rhl[tile][1] + rlh[tile][1]);
        *(float2*)&out_res[((size_t)b * TT + row + 8) * DD + col] =
            make_float2(rhh[tile][2] + rhl[tile][2] + rlh[tile][2],
                        rhh[tile][3] + rhl[tile][3] + rlh[tile][3]);
    }
}

extern "C" void kernel_launch(void* const* d_in, const int* in_sizes, int n_in,
                              void* d_out, int out_size) {
    const float* key   = (const float*)d_in[0];
    const float* value = (const float*)d_in[1];
    const float* query = (const float*)d_in[2];
    const void*  mask  = d_in[3];
    const float* qmask = (const float*)d_in[4];

    float* out      = (float*)d_out;
    float* out_res  = out;                          // [B, T, D] first (tuple order)
    float* out_attn = out + (size_t)BB * TT * DD;   // [B, T, T] second

    prep_kernel<<<6145, 512>>>(query, key, value, (const unsigned char*)mask);

    cudaFuncSetAttribute(mh_attn_mma5_kernel,
                         cudaFuncAttributeMaxDynamicSharedMemorySize, SM_TOTAL);
    dim3 grid(BB * (TT / QT));   // 2048 CTAs
    mh_attn_mma5_kernel<<<grid, NTHREADS, SM_TOTAL>>>(mask, qmask, out_res, out_attn);
}

// round 9
// speedup vs baseline: 1.1938x; 1.1938x over previous
#include <cuda_runtime.h>
#include <cuda_bf16.h>

typedef unsigned int u32;

#define BB 64
#define TT 1024
#define DD 128
#define QT 32                  // q rows per CTA
#define KT 64                  // k-seq tile
#define NTHREADS 512
#define SSTRIDE 1032
#define SCALE 0.08838834764831845f
#define LOG2E 1.4426950408889634f
// scores live in log2 domain; masked fill = huge negative (exp2 -> 0)
#define MASK_FILL_L2 (-6.0e9f)

// ---- smem layout (bytes) ----
#define SM_SS    0                          // 32 x 1032 f32 scores (132096)
#define SM_KV    132096                     // 2 stages x {hi 16KB, lo 16KB}
#define SM_QP    (SM_KV + 2*32768)          // phase1: Q image hi/lo (8KB+8KB)
                                            // phase3: 2 P stages x {hi 4KB, lo 4KB}
#define SM_TOTAL (SM_QP + 16384)            // 214016

// 256B-row tiles: 16B unit `unit` of row `row`
#define SWZ_UNIT(row, unit) ((u32)(row) * 256u + (((u32)(unit) ^ ((u32)(row) & 7u)) << 4))
// 128B-row tiles (P): 8 units per row
#define SWZP_UNIT(row, unit) ((u32)(row) * 128u + (((u32)(unit) ^ ((u32)(row) & 7u)) << 4))

// ---- precomputed bf16 hi/lo operand images (swizzled smem-identical tiles) ----
__device__ __align__(16) unsigned char g_QHI[1 << 24];
__device__ __align__(16) unsigned char g_QLO[1 << 24];
__device__ __align__(16) unsigned char g_KHI[1 << 24];
__device__ __align__(16) unsigned char g_KLO[1 << 24];
__device__ __align__(16) unsigned char g_VHI[1 << 24];
__device__ __align__(16) unsigned char g_VLO[1 << 24];

// ================= PTX helpers =================
__device__ __forceinline__ u32 smem_u32(const void* p) {
    u32 a;
    asm("{ .reg .u64 t; cvta.to.shared.u64 t, %1; cvt.u32.u64 %0, t; }" : "=r"(a) : "l"(p));
    return a;
}
__device__ __forceinline__ void cp16(u32 dst, const void* src) {
    asm volatile("cp.async.cg.shared.global [%0], [%1], 16;" :: "r"(dst), "l"(src));
}
#define CP_COMMIT() asm volatile("cp.async.commit_group;" ::: "memory")
#define CP_WAIT_ALL() asm volatile("cp.async.wait_group 0;" ::: "memory")

__device__ __forceinline__ void ldm_x4(u32* r, u32 addr) {
    asm volatile("ldmatrix.sync.aligned.m8n8.x4.shared.b16 {%0,%1,%2,%3}, [%4];"
                 : "=r"(r[0]), "=r"(r[1]), "=r"(r[2]), "=r"(r[3]) : "r"(addr));
}
__device__ __forceinline__ void ldm_x4t(u32* r, u32 addr) {
    asm volatile("ldmatrix.sync.aligned.m8n8.x4.trans.shared.b16 {%0,%1,%2,%3}, [%4];"
                 : "=r"(r[0]), "=r"(r[1]), "=r"(r[2]), "=r"(r[3]) : "r"(addr));
}
__device__ __forceinline__ void mma16816(float* c, const u32* a, const u32* b) {
    asm volatile(
        "mma.sync.aligned.m16n8k16.row.col.f32.bf16.bf16.f32 "
        "{%0,%1,%2,%3}, {%4,%5,%6,%7}, {%8,%9}, {%0,%1,%2,%3};"
        : "+f"(c[0]), "+f"(c[1]), "+f"(c[2]), "+f"(c[3])
        : "r"(a[0]), "r"(a[1]), "r"(a[2]), "r"(a[3]), "r"(b[0]), "r"(b[1]));
}
__device__ __forceinline__ void cvt_split2(float x0, float x1, u32& hi, u32& lo) {
    __nv_bfloat16 h0 = __float2bfloat16(x0);
    __nv_bfloat16 h1 = __float2bfloat16(x1);
    __nv_bfloat16 l0 = __float2bfloat16(x0 - __bfloat162float(h0));
    __nv_bfloat16 l1 = __float2bfloat16(x1 - __bfloat162float(h1));
    __nv_bfloat162 H(h0, h1), L(l0, l1);
    hi = *reinterpret_cast<u32*>(&H);
    lo = *reinterpret_cast<u32*>(&L);
}

// ---- exp2 two ways: MUFU pipe and FFMA-pipe polynomial ----
__device__ __forceinline__ float exp2_mufu(float v) {
    float r;
    asm("ex2.approx.f32 %0, %1;" : "=f"(r) : "f"(v));
    return r;
}
__device__ __forceinline__ float exp2_poly(float v) {
    v = fmaxf(v, -126.0f);
    float f = v + 12582912.0f;                 // round-to-nearest integer (magic)
    int n = __float_as_int(f) - 0x4B400000;    // integer part
    float r = v - (f - 12582912.0f);           // r in [-0.5, 0.5]
    float p = fmaf(r, 0.0013333558f, 0.009618129f);
    p = fmaf(p, r, 0.05550411f);
    p = fmaf(p, r, 0.2402265f);
    p = fmaf(p, r, 0.6931472f);
    p = fmaf(p, r, 1.0f);
    return __int_as_float(__float_as_int(p) + (n << 23));
}

// ---------------- mask dtype probe + mode ----------------
__device__ int g_mask_mode;   // 0=u8, 1=i32, 2=f32

__device__ __forceinline__ bool mask_at(const void* __restrict__ m, size_t idx, int mode)
{
    if (mode == 0) return ((const unsigned char*)m)[idx] != 0;
    if (mode == 1) return ((const int*)m)[idx] != 0;
    return ((const float*)m)[idx] != 0.0f;
}

// ---------------- prep: f32 -> bf16 hi/lo swizzled tile images (+ mask probe) ----------------
__global__ __launch_bounds__(512)
void prep_kernel(const float* __restrict__ query,
                 const float* __restrict__ key,
                 const float* __restrict__ value,
                 const unsigned char* __restrict__ mask)
{
    if (blockIdx.x == 6144) {   // probe block (warp 0 only)
        if (threadIdx.x >= 32) return;
        const int lane = threadIdx.x;
        const float* mf = (const float*)mask;
        bool f01 = true;
        for (int i = lane; i < 1024; i += 32) {
            float f = mf[i];
            if (f != 0.0f && f != 1.0f) f01 = false;
        }
        if (__all_sync(0xffffffffu, f01)) {
            if (lane == 0) g_mask_mode = 2;
            return;
        }
        u32 any_high = 0;
        for (int i = lane * 4; i < 4096; i += 128)
            any_high |= (mask[i + 1] | mask[i + 2] | mask[i + 3]);
        int any = __any_sync(0xffffffffu, any_high != 0);
        if (lane == 0) g_mask_mode = any ? 0 : 1;
        return;
    }

    int idx = blockIdx.x * blockDim.x + threadIdx.x;   // 3 * 1048576 total
    int tensor = idx >> 20;
    int u = idx & 1048575;           // b(6) | seq(10) | unit(4)
    int unit = u & 15;
    int seq = (u >> 4) & 1023;
    int b = u >> 14;

    const float* src;
    unsigned char *dhi, *dlo;
    float scale = 1.0f;
    size_t img;
    int r;
    if (tensor == 0) {
        src = query; dhi = g_QHI; dlo = g_QLO; scale = SCALE * LOG2E;  // log2 domain
        img = (size_t)(b * 32 + (seq >> 5)) << 13; r = seq & 31;
    } else if (tensor == 1) {
        src = key; dhi = g_KHI; dlo = g_KLO;
        img = (size_t)(b * 16 + (seq >> 6)) << 14; r = seq & 63;
    } else {
        src = value; dhi = g_VHI; dlo = g_VLO;
        img = (size_t)(b * 16 + (seq >> 6)) << 14; r = seq & 63;
    }
    const float4* s4 = (const float4*)(src + ((size_t)b * TT + seq) * DD + unit * 8);
    float4 x0 = s4[0], x1 = s4[1];
    uint4 H, L;
    cvt_split2(x0.x * scale, x0.y * scale, H.x, L.x);
    cvt_split2(x0.z * scale, x0.w * scale, H.y, L.y);
    cvt_split2(x1.x * scale, x1.y * scale, H.z, L.z);
    cvt_split2(x1.z * scale, x1.w * scale, H.w, L.w);
    u32 off = (u32)r * 256u + (((u32)(unit ^ (r & 7))) << 4);
    *(uint4*)(dhi + img + off) = H;
    *(uint4*)(dlo + img + off) = L;
}

// ---------------- tile copy helpers ----------------
__device__ __forceinline__ void copy_kv_tile(u32 dst, const unsigned char* ghi,
                                             const unsigned char* glo, size_t base, int tid)
{
    #pragma unroll
    for (int i = 0; i < 2; ++i) {
        int c = tid + i * 512;
        cp16(dst + c * 16, ghi + base + (size_t)c * 16);
        cp16(dst + 16384 + c * 16, glo + base + (size_t)c * 16);
    }
}

// ================= fused attention =================
__global__ __launch_bounds__(NTHREADS, 1)
void mh_attn_mma6_kernel(const void* __restrict__ mask,
                         const float* __restrict__ qmask,
                         float* __restrict__ out_res,
                         float* __restrict__ out_attn)
{
    extern __shared__ char smem[];
    float* sS = (float*)smem;
    const u32 sb = smem_u32(smem);

    const int b    = blockIdx.x >> 5;
    const int q0   = (blockIdx.x & 31) * QT;
    const int tid  = threadIdx.x;
    const int wid  = tid >> 5;
    const int lane = tid & 31;
    const int grp  = lane >> 3;
    const int sub  = lane & 7;
    const int g    = lane >> 2;
    const int t    = lane & 3;
    const int wm   = wid & 1;
    const int wn   = wid >> 1;      // 0..7
    const int m0   = wm * 16;

    // ---- preload Q image + K tile 0 ----
    {
        size_t qimg = (size_t)(b * 32 + (q0 >> 5)) << 13;
        cp16(sb + SM_QP + tid * 16, g_QHI + qimg + (size_t)tid * 16);
        cp16(sb + SM_QP + 8192 + tid * 16, g_QLO + qimg + (size_t)tid * 16);
        copy_kv_tile(sb + SM_KV, g_KHI, g_KLO, (size_t)(b * 16) << 14, tid);
        CP_COMMIT();
        CP_WAIT_ALL();
    }
    __syncthreads();

    // ---- cache Q fragments (m16 x k128, hi+lo) ----
    u32 qhi[8][4], qlo[8][4];
    {
        int rowA = m0 + sub + ((grp & 1) << 3);
        #pragma unroll
        for (int ks = 0; ks < 8; ++ks) {
            u32 off = SWZ_UNIT(rowA, 2 * ks + (grp >> 1));
            ldm_x4(qhi[ks], sb + SM_QP + off);
            ldm_x4(qlo[ks], sb + SM_QP + 8192 + off);
        }
    }

    // =========== Phase 1: S' = (Q*scale*log2e) @ K^T -> sS ===========
    {
        const int rowB   = wn * 8 + sub;
        const u32 hilo   = (grp >> 1) ? 16384u : 0u;
        for (int kt = 0; kt < TT / KT; ++kt) {
            if (kt < 15) {
                copy_kv_tile(sb + SM_KV + ((kt + 1) & 1) * 32768,
                             g_KHI, g_KLO, (size_t)(b * 16 + kt + 1) << 14, tid);
                CP_COMMIT();
            }
            const u32 stage = sb + SM_KV + (kt & 1) * 32768 + hilo;
            float ahh[4] = {0.f,0.f,0.f,0.f};
            float ahl[4] = {0.f,0.f,0.f,0.f};
            float alh[4] = {0.f,0.f,0.f,0.f};
            #pragma unroll
            for (int ks = 0; ks < 8; ++ks) {
                u32 bb[4];   // bb[0..1]=bhi, bb[2..3]=blo (lane-mixed tiles)
                ldm_x4(bb, stage + SWZ_UNIT(rowB, 2 * ks + (grp & 1)));
                mma16816(ahh, qhi[ks], bb);
                mma16816(ahl, qhi[ks], bb + 2);
                mma16816(alh, qlo[ks], bb);
            }
            int col = kt * KT + wn * 8 + 2 * t;
            *(float2*)&sS[(m0 + g) * SSTRIDE + col] =
                make_float2(ahh[0] + ahl[0] + alh[0], ahh[1] + ahl[1] + alh[1]);
            *(float2*)&sS[(m0 + g + 8) * SSTRIDE + col] =
                make_float2(ahh[2] + ahl[2] + alh[2], ahh[3] + ahl[3] + alh[3]);
            if (kt < 15) CP_WAIT_ALL();
            __syncthreads();
        }
    }

    // ---- prefetch V tile 0 (bufKV idle during softmax) ----
    copy_kv_tile(sb + SM_KV, g_VHI, g_VLO, (size_t)(b * 16) << 14, tid);
    CP_COMMIT();

    // =========== Phase 2: register-resident softmax (1R + 1W per element) ===========
    {
        const int mmode = g_mask_mode;
        float* attn_g = out_attn + ((size_t)b * TT + q0) * TT;
        for (int r = wid; r < QT; r += 16) {
            float* row = sS + r * SSTRIDE;
            const size_t mrow = (size_t)b * TT * TT + (size_t)(q0 + r) * TT;

            float sv[32];
            float mx = -3.402823466e38f;
            #pragma unroll
            for (int j = 0; j < 32; ++j) {
                int i = lane + 32 * j;
                float s = row[i];
                if (mask_at(mask, mrow + i, mmode)) s = MASK_FILL_L2;
                sv[j] = s;
                mx = fmaxf(mx, s);
            }
            #pragma unroll
            for (int o = 16; o; o >>= 1) mx = fmaxf(mx, __shfl_xor_sync(0xffffffffu, mx, o));

            // exp2: 3/5 MUFU, 2/5 FFMA-poly (concurrent pipes)
            float sum0 = 0.f, sum1 = 0.f;
            #pragma unroll
            for (int j = 0; j < 32; ++j) {
                float v = sv[j] - mx;
                float e = ((j % 5) < 3) ? exp2_mufu(v) : exp2_poly(v);
                sv[j] = e;
                if (j & 1) sum1 += e; else sum0 += e;
            }
            float sum = sum0 + sum1;
            #pragma unroll
            for (int o = 16; o; o >>= 1) sum += __shfl_xor_sync(0xffffffffu, sum, o);
            float inv = qmask[(size_t)b * TT + q0 + r] / sum;

            #pragma unroll
            for (int j = 0; j < 32; ++j) {
                int i = lane + 32 * j;
                float v = sv[j] * inv;
                row[i] = v;
                attn_g[(size_t)r * TT + i] = v;
            }
        }
    }
    __syncthreads();

    // =========== Phase 3: result = P @ V ===========
    float rhh[2][4] = {{0.f,0.f,0.f,0.f},{0.f,0.f,0.f,0.f}};
    float rhl[2][4] = {{0.f,0.f,0.f,0.f},{0.f,0.f,0.f,0.f}};
    float rlh[2][4] = {{0.f,0.f,0.f,0.f},{0.f,0.f,0.f,0.f}};
    {
        auto convert_P = [&](int kt) {
            char* ps = smem + SM_QP + (kt & 1) * 8192;
            #pragma unroll
            for (int i = 0; i < 2; ++i) {
                int j = tid + i * 512;
                int r = j >> 5, c2 = j & 31;
                float2 p2 = *(const float2*)&sS[r * SSTRIDE + kt * KT + 2 * c2];
                u32 hi, lo;
                cvt_split2(p2.x, p2.y, hi, lo);
                u32 off = SWZP_UNIT(r, c2 >> 2) + ((c2 & 3) << 2);
                *(u32*)(ps + off) = hi;
                *(u32*)(ps + 4096 + off) = lo;
            }
        };

        convert_P(0);          // V tile 0 already in flight (prefetched pre-softmax)
        CP_WAIT_ALL();
        __syncthreads();

        const int rowA  = m0 + sub + ((grp & 1) << 3);
        const int rowB0 = sub + ((grp & 1) << 3);
        const int unitB = 2 * wn + (grp >> 1);

        for (int kt = 0; kt < TT / KT; ++kt) {
            if (kt < 15) {
                copy_kv_tile(sb + SM_KV + ((kt + 1) & 1) * 32768,
                             g_VHI, g_VLO, (size_t)(b * 16 + kt + 1) << 14, tid);
                CP_COMMIT();
            }
            const u32 stV = sb + SM_KV + (kt & 1) * 32768;
            const u32 stP = sb + SM_QP + (kt & 1) * 8192;
            #pragma unroll
            for (int ks = 0; ks < 4; ++ks) {
                u32 offA = SWZP_UNIT(rowA, 2 * ks + (grp >> 1));
                u32 ah[4], al[4];
                ldm_x4(ah, stP + offA);
                ldm_x4(al, stP + 4096 + offA);
                u32 offB = SWZ_UNIT(ks * 16 + rowB0, unitB);
                u32 bh[4], bl[4];
                ldm_x4t(bh, stV + offB);
                ldm_x4t(bl, stV + 16384 + offB);
                #pragma unroll
                for (int tile = 0; tile < 2; ++tile) {
                    mma16816(rhh[tile], ah, bh + 2 * tile);
                    mma16816(rhl[tile], ah, bl + 2 * tile);
                    mma16816(rlh[tile], al, bh + 2 * tile);
                }
            }
            if (kt < 15) {
                convert_P(kt + 1);
                CP_WAIT_ALL();
                __syncthreads();
            }
        }
    }

    // ---- result epilogue ----
    #pragma unroll
    for (int tile = 0; tile < 2; ++tile) {
        int col = wn * 16 + tile * 8 + 2 * t;
        int row = q0 + m0 + g;
        *(float2*)&out_res[((size_t)b * TT + row) * DD + col] =
            make_float2(rhh[tile][0] + rhl[tile][0] + rlh[tile][0],
                        rhh[tile][1] + rhl[tile][1] + rlh[tile][1]);
        *(float2*)&out_res[((size_t)b * TT + row + 8) * DD + col] =
            make_float2(rhh[tile][2] + rhl[tile][2] + rlh[tile][2],
                        rhh[tile][3] + rhl[tile][3] + rlh[tile][3]);
    }
}

extern "C" void kernel_launch(void* const* d_in, const int* in_sizes, int n_in,
                              void* d_out, int out_size) {
    const float* key   = (const float*)d_in[0];
    const float* value = (const float*)d_in[1];
    const float* query = (const float*)d_in[2];
    const void*  mask  = d_in[3];
    const float* qmask = (const float*)d_in[4];

    float* out      = (float*)d_out;
    float* out_res  = out;                          // [B, T, D] first (tuple order)
    float* out_attn = out + (size_t)BB * TT * DD;   // [B, T, T] second

    prep_kernel<<<6145, 512>>>(query, key, value, (const unsigned char*)mask);

    cudaFuncSetAttribute(mh_attn_mma6_kernel,
                         cudaFuncAttributeMaxDynamicSharedMemorySize, SM_TOTAL);
    dim3 grid(BB * (TT / QT));   // 2048 CTAs
    mh_attn_mma6_kernel<<<grid, NTHREADS, SM_TOTAL>>>(mask, qmask, out_res, out_attn);
}

// round 10
// speedup vs baseline: 1.2562x; 1.0523x over previous
#include <cuda_runtime.h>
#include <cuda_bf16.h>

typedef unsigned int u32;

#define BB 64
#define TT 1024
#define DD 128
#define QT 32                  // q rows per CTA
#define KT 64                  // k-seq tile
#define NTHREADS 512
#define SSTRIDE 1032
#define ROWB (SSTRIDE*4)       // 4128 bytes per score row
#define SCALE 0.08838834764831845f
#define LOG2E 1.4426950408889634f
// scores live in log2 domain; masked fill = huge negative (exp2 -> 0)
#define MASK_FILL_L2 (-6.0e9f)

// ---- smem layout (bytes) ----
#define SM_SS    0                          // 32 x 1032 f32 scores (132096)
                                            // phase>=2: per-row bf16 P hi [0,2048) lo [2048,4096)
#define SM_KV    132096                     // 2 stages x {hi 16KB, lo 16KB}
#define SM_QP    (SM_KV + 2*32768)          // Q image hi/lo (8KB+8KB)
#define SM_TOTAL (SM_QP + 16384)            // 214016

// 256B-row tiles: 16B unit `unit` of row `row`
#define SWZ_UNIT(row, unit) ((u32)(row) * 256u + (((u32)(unit) ^ ((u32)(row) & 7u)) << 4))

// ---- precomputed bf16 hi/lo operand images (swizzled smem-identical tiles) ----
__device__ __align__(16) unsigned char g_QHI[1 << 24];
__device__ __align__(16) unsigned char g_QLO[1 << 24];
__device__ __align__(16) unsigned char g_KHI[1 << 24];
__device__ __align__(16) unsigned char g_KLO[1 << 24];
__device__ __align__(16) unsigned char g_VHI[1 << 24];
__device__ __align__(16) unsigned char g_VLO[1 << 24];

// ================= PTX helpers =================
__device__ __forceinline__ u32 smem_u32(const void* p) {
    u32 a;
    asm("{ .reg .u64 t; cvta.to.shared.u64 t, %1; cvt.u32.u64 %0, t; }" : "=r"(a) : "l"(p));
    return a;
}
__device__ __forceinline__ void cp16(u32 dst, const void* src) {
    asm volatile("cp.async.cg.shared.global [%0], [%1], 16;" :: "r"(dst), "l"(src));
}
#define CP_COMMIT() asm volatile("cp.async.commit_group;" ::: "memory")
#define CP_WAIT_ALL() asm volatile("cp.async.wait_group 0;" ::: "memory")

__device__ __forceinline__ void ldm_x4(u32* r, u32 addr) {
    asm volatile("ldmatrix.sync.aligned.m8n8.x4.shared.b16 {%0,%1,%2,%3}, [%4];"
                 : "=r"(r[0]), "=r"(r[1]), "=r"(r[2]), "=r"(r[3]) : "r"(addr));
}
__device__ __forceinline__ void ldm_x4t(u32* r, u32 addr) {
    asm volatile("ldmatrix.sync.aligned.m8n8.x4.trans.shared.b16 {%0,%1,%2,%3}, [%4];"
                 : "=r"(r[0]), "=r"(r[1]), "=r"(r[2]), "=r"(r[3]) : "r"(addr));
}
__device__ __forceinline__ void mma16816(float* c, const u32* a, const u32* b) {
    asm volatile(
        "mma.sync.aligned.m16n8k16.row.col.f32.bf16.bf16.f32 "
        "{%0,%1,%2,%3}, {%4,%5,%6,%7}, {%8,%9}, {%0,%1,%2,%3};"
        : "+f"(c[0]), "+f"(c[1]), "+f"(c[2]), "+f"(c[3])
        : "r"(a[0]), "r"(a[1]), "r"(a[2]), "r"(a[3]), "r"(b[0]), "r"(b[1]));
}
__device__ __forceinline__ void cvt_split2(float x0, float x1, u32& hi, u32& lo) {
    __nv_bfloat16 h0 = __float2bfloat16(x0);
    __nv_bfloat16 h1 = __float2bfloat16(x1);
    __nv_bfloat16 l0 = __float2bfloat16(x0 - __bfloat162float(h0));
    __nv_bfloat16 l1 = __float2bfloat16(x1 - __bfloat162float(h1));
    __nv_bfloat162 H(h0, h1), L(l0, l1);
    hi = *reinterpret_cast<u32*>(&H);
    lo = *reinterpret_cast<u32*>(&L);
}

// ---- exp2 two ways: MUFU pipe and FFMA-pipe polynomial ----
__device__ __forceinline__ float exp2_mufu(float v) {
    float r;
    asm("ex2.approx.f32 %0, %1;" : "=f"(r) : "f"(v));
    return r;
}
__device__ __forceinline__ float exp2_poly(float v) {
    v = fmaxf(v, -126.0f);
    float f = v + 12582912.0f;                 // round-to-nearest integer (magic)
    int n = __float_as_int(f) - 0x4B400000;    // integer part
    float r = v - (f - 12582912.0f);           // r in [-0.5, 0.5]
    float p = fmaf(r, 0.0013333558f, 0.009618129f);
    p = fmaf(p, r, 0.05550411f);
    p = fmaf(p, r, 0.2402265f);
    p = fmaf(p, r, 0.6931472f);
    p = fmaf(p, r, 1.0f);
    return __int_as_float(__float_as_int(p) + (n << 23));
}

// ---------------- mask dtype probe + mode ----------------
__device__ int g_mask_mode;   // 0=u8, 1=i32, 2=f32

// ---------------- prep: f32 -> bf16 hi/lo swizzled tile images (+ mask probe) ----------------
__global__ __launch_bounds__(512)
void prep_kernel(const float* __restrict__ query,
                 const float* __restrict__ key,
                 const float* __restrict__ value,
                 const unsigned char* __restrict__ mask)
{
    if (blockIdx.x == 6144) {   // probe block (warp 0 only)
        if (threadIdx.x >= 32) return;
        const int lane = threadIdx.x;
        const float* mf = (const float*)mask;
        bool f01 = true;
        for (int i = lane; i < 1024; i += 32) {
            float f = mf[i];
            if (f != 0.0f && f != 1.0f) f01 = false;
        }
        if (__all_sync(0xffffffffu, f01)) {
            if (lane == 0) g_mask_mode = 2;
            return;
        }
        u32 any_high = 0;
        for (int i = lane * 4; i < 4096; i += 128)
            any_high |= (mask[i + 1] | mask[i + 2] | mask[i + 3]);
        int any = __any_sync(0xffffffffu, any_high != 0);
        if (lane == 0) g_mask_mode = any ? 0 : 1;
        return;
    }

    int idx = blockIdx.x * blockDim.x + threadIdx.x;   // 3 * 1048576 total
    int tensor = idx >> 20;
    int u = idx & 1048575;           // b(6) | seq(10) | unit(4)
    int unit = u & 15;
    int seq = (u >> 4) & 1023;
    int b = u >> 14;

    const float* src;
    unsigned char *dhi, *dlo;
    float scale = 1.0f;
    size_t img;
    int r;
    if (tensor == 0) {
        src = query; dhi = g_QHI; dlo = g_QLO; scale = SCALE * LOG2E;  // log2 domain
        img = (size_t)(b * 32 + (seq >> 5)) << 13; r = seq & 31;
    } else if (tensor == 1) {
        src = key; dhi = g_KHI; dlo = g_KLO;
        img = (size_t)(b * 16 + (seq >> 6)) << 14; r = seq & 63;
    } else {
        src = value; dhi = g_VHI; dlo = g_VLO;
        img = (size_t)(b * 16 + (seq >> 6)) << 14; r = seq & 63;
    }
    const float4* s4 = (const float4*)(src + ((size_t)b * TT + seq) * DD + unit * 8);
    float4 x0 = s4[0], x1 = s4[1];
    uint4 H, L;
    cvt_split2(x0.x * scale, x0.y * scale, H.x, L.x);
    cvt_split2(x0.z * scale, x0.w * scale, H.y, L.y);
    cvt_split2(x1.x * scale, x1.y * scale, H.z, L.z);
    cvt_split2(x1.z * scale, x1.w * scale, H.w, L.w);
    u32 off = (u32)r * 256u + (((u32)(unit ^ (r & 7))) << 4);
    *(uint4*)(dhi + img + off) = H;
    *(uint4*)(dlo + img + off) = L;
}

// ---------------- tile copy helpers ----------------
__device__ __forceinline__ void copy_kv_tile(u32 dst, const unsigned char* ghi,
                                             const unsigned char* glo, size_t base, int tid)
{
    #pragma unroll
    for (int i = 0; i < 2; ++i) {
        int c = tid + i * 512;
        cp16(dst + c * 16, ghi + base + (size_t)c * 16);
        cp16(dst + 16384 + c * 16, glo + base + (size_t)c * 16);
    }
}

// ================= fused attention =================
__global__ __launch_bounds__(NTHREADS, 1)
void mh_attn_mma7_kernel(const void* __restrict__ mask,
                         const float* __restrict__ qmask,
                         float* __restrict__ out_res,
                         float* __restrict__ out_attn)
{
    extern __shared__ char smem[];
    float* sS = (float*)smem;
    const u32 sb = smem_u32(smem);

    const int b    = blockIdx.x >> 5;
    const int q0   = (blockIdx.x & 31) * QT;
    const int tid  = threadIdx.x;
    const int wid  = tid >> 5;
    const int lane = tid & 31;
    const int grp  = lane >> 3;
    const int sub  = lane & 7;
    const int g    = lane >> 2;
    const int t    = lane & 3;
    const int wm   = wid & 1;
    const int wn   = wid >> 1;      // 0..7
    const int m0   = wm * 16;

    // ---- preload Q image + K tile 0 ----
    {
        size_t qimg = (size_t)(b * 32 + (q0 >> 5)) << 13;
        cp16(sb + SM_QP + tid * 16, g_QHI + qimg + (size_t)tid * 16);
        cp16(sb + SM_QP + 8192 + tid * 16, g_QLO + qimg + (size_t)tid * 16);
        copy_kv_tile(sb + SM_KV, g_KHI, g_KLO, (size_t)(b * 16) << 14, tid);
        CP_COMMIT();
        CP_WAIT_ALL();
    }
    __syncthreads();

    // ---- cache Q fragments (m16 x k128, hi+lo) ----
    u32 qhi[8][4], qlo[8][4];
    {
        int rowA = m0 + sub + ((grp & 1) << 3);
        #pragma unroll
        for (int ks = 0; ks < 8; ++ks) {
            u32 off = SWZ_UNIT(rowA, 2 * ks + (grp >> 1));
            ldm_x4(qhi[ks], sb + SM_QP + off);
            ldm_x4(qlo[ks], sb + SM_QP + 8192 + off);
        }
    }

    // =========== Phase 1: S' = (Q*scale*log2e) @ K^T -> sS (f32) ===========
    {
        const int rowB   = wn * 8 + sub;
        const u32 hilo   = (grp >> 1) ? 16384u : 0u;
        for (int kt = 0; kt < TT / KT; ++kt) {
            if (kt < 15) {
                copy_kv_tile(sb + SM_KV + ((kt + 1) & 1) * 32768,
                             g_KHI, g_KLO, (size_t)(b * 16 + kt + 1) << 14, tid);
                CP_COMMIT();
            }
            const u32 stage = sb + SM_KV + (kt & 1) * 32768 + hilo;
            float ahh[4] = {0.f,0.f,0.f,0.f};
            float ahl[4] = {0.f,0.f,0.f,0.f};
            float alh[4] = {0.f,0.f,0.f,0.f};
            #pragma unroll
            for (int ks = 0; ks < 8; ++ks) {
                u32 bb[4];   // bb[0..1]=bhi, bb[2..3]=blo (lane-mixed tiles)
                ldm_x4(bb, stage + SWZ_UNIT(rowB, 2 * ks + (grp & 1)));
                mma16816(ahh, qhi[ks], bb);
                mma16816(ahl, qhi[ks], bb + 2);
                mma16816(alh, qlo[ks], bb);
            }
            int col = kt * KT + wn * 8 + 2 * t;
            *(float2*)&sS[(m0 + g) * SSTRIDE + col] =
                make_float2(ahh[0] + ahl[0] + alh[0], ahh[1] + ahl[1] + alh[1]);
            *(float2*)&sS[(m0 + g + 8) * SSTRIDE + col] =
                make_float2(ahh[2] + ahl[2] + alh[2], ahh[3] + ahl[3] + alh[3]);
            if (kt < 15) CP_WAIT_ALL();
            __syncthreads();
        }
    }

    // ---- prefetch V tile 0 (bufKV idle during softmax) ----
    copy_kv_tile(sb + SM_KV, g_VHI, g_VLO, (size_t)(b * 16) << 14, tid);
    CP_COMMIT();

    // =========== Phase 2: softmax + in-place bf16 P conversion ===========
    // Each warp owns full rows; reads f32 scores, writes final attn to gmem
    // AND overwrites its own row storage with bf16 hi [0,2048) / lo [2048,4096).
    {
        const int mmode = g_mask_mode;
        float* attn_g = out_attn + ((size_t)b * TT + q0) * TT;
        for (int r = wid; r < QT; r += 16) {
            char* rowb = smem + SM_SS + r * ROWB;
            const size_t mrow = (size_t)b * TT * TT + (size_t)(q0 + r) * TT;

            float2 sv[16];
            float mx = -3.402823466e38f;
            #pragma unroll
            for (int jj = 0; jj < 16; ++jj) {
                int c2 = lane + 32 * jj;            // element pair index
                float2 s2 = *(const float2*)(rowb + 8 * c2);
                bool k0, k1;
                if (mmode == 0) {
                    const unsigned char* mp = (const unsigned char*)mask + mrow + 2 * c2;
                    k0 = mp[0] != 0; k1 = mp[1] != 0;
                } else if (mmode == 1) {
                    int2 mv = *(const int2*)((const int*)mask + mrow + 2 * c2);
                    k0 = mv.x != 0; k1 = mv.y != 0;
                } else {
                    float2 mv = *(const float2*)((const float*)mask + mrow + 2 * c2);
                    k0 = mv.x != 0.0f; k1 = mv.y != 0.0f;
                }
                if (k0) s2.x = MASK_FILL_L2;
                if (k1) s2.y = MASK_FILL_L2;
                sv[jj] = s2;
                mx = fmaxf(mx, fmaxf(s2.x, s2.y));
            }
            #pragma unroll
            for (int o = 16; o; o >>= 1) mx = fmaxf(mx, __shfl_xor_sync(0xffffffffu, mx, o));

            // exp2: 3/5 MUFU, 2/5 FFMA-poly (concurrent pipes)
            float sum0 = 0.f, sum1 = 0.f;
            #pragma unroll
            for (int jj = 0; jj < 16; ++jj) {
                float v0 = sv[jj].x - mx, v1 = sv[jj].y - mx;
                float e0 = (((2 * jj) % 5) < 3) ? exp2_mufu(v0) : exp2_poly(v0);
                float e1 = (((2 * jj + 1) % 5) < 3) ? exp2_mufu(v1) : exp2_poly(v1);
                sv[jj].x = e0; sv[jj].y = e1;
                sum0 += e0; sum1 += e1;
            }
            float sum = sum0 + sum1;
            #pragma unroll
            for (int o = 16; o; o >>= 1) sum += __shfl_xor_sync(0xffffffffu, sum, o);
            float inv = qmask[(size_t)b * TT + q0 + r] / sum;

            __syncwarp();   // all f32 reads of this row complete before overwrite
            #pragma unroll
            for (int jj = 0; jj < 16; ++jj) {
                int c2 = lane + 32 * jj;
                float a0 = sv[jj].x * inv, a1 = sv[jj].y * inv;
                *(float2*)(attn_g + (size_t)r * TT + 2 * c2) = make_float2(a0, a1);
                u32 hi, lo;
                cvt_split2(a0, a1, hi, lo);
                u32 off = ((u32)((c2 >> 2) ^ (r & 7)) << 4) + ((u32)(c2 & 3) << 2);
                *(u32*)(rowb + off) = hi;
                *(u32*)(rowb + 2048 + off) = lo;
            }
        }
    }
    __syncthreads();

    // =========== Phase 3: result = P @ V (P ldmatrix'd straight from sS) ===========
    float rhh[2][4] = {{0.f,0.f,0.f,0.f},{0.f,0.f,0.f,0.f}};
    float rhl[2][4] = {{0.f,0.f,0.f,0.f},{0.f,0.f,0.f,0.f}};
    float rlh[2][4] = {{0.f,0.f,0.f,0.f},{0.f,0.f,0.f,0.f}};
    {
        CP_WAIT_ALL();   // V tile 0
        __syncthreads();

        const int rowA  = m0 + sub + ((grp & 1) << 3);
        const int rowB0 = sub + ((grp & 1) << 3);
        const int unitB = 2 * wn + (grp >> 1);
        const u32 pbase = sb + SM_SS + (u32)rowA * ROWB;   // this lane's P row
        const u32 prx   = (u32)(rowA & 7);

        for (int kt = 0; kt < TT / KT; ++kt) {
            if (kt < 15) {
                copy_kv_tile(sb + SM_KV + ((kt + 1) & 1) * 32768,
                             g_VHI, g_VLO, (size_t)(b * 16 + kt + 1) << 14, tid);
                CP_COMMIT();
            }
            const u32 stV = sb + SM_KV + (kt & 1) * 32768;
            #pragma unroll
            for (int ks = 0; ks < 4; ++ks) {
                u32 U = (u32)(8 * kt + 2 * ks + (grp >> 1));
                u32 offA = (U ^ prx) << 4;
                u32 ah[4], al[4];
                ldm_x4(ah, pbase + offA);
                ldm_x4(al, pbase + 2048 + offA);
                u32 offB = SWZ_UNIT(ks * 16 + rowB0, unitB);
                u32 bh[4], bl[4];
                ldm_x4t(bh, stV + offB);
                ldm_x4t(bl, stV + 16384 + offB);
                #pragma unroll
                for (int tile = 0; tile < 2; ++tile) {
                    mma16816(rhh[tile], ah, bh + 2 * tile);
                    mma16816(rhl[tile], ah, bl + 2 * tile);
                    mma16816(rlh[tile], al, bh + 2 * tile);
                }
            }
            if (kt < 15) {
                CP_WAIT_ALL();
                __syncthreads();
            }
        }
    }

    // ---- result epilogue ----
    #pragma unroll
    for (int tile = 0; tile < 2; ++tile) {
        int col = wn * 16 + tile * 8 + 2 * t;
        int row = q0 + m0 + g;
        *(float2*)&out_res[((size_t)b * TT + row) * DD + col] =
            make_float2(rhh[tile][0] + rhl[tile][0] + rlh[tile][0],
                        rhh[tile][1] + rhl[tile][1] + rlh[tile][1]);
        *(float2*)&out_res[((size_t)b * TT + row + 8) * DD + col] =
            make_float2(rhh[tile][2] + rhl[tile][2] + rlh[tile][2],
                        rhh[tile][3] + rhl[tile][3] + rlh[tile][3]);
    }
}

extern "C" void kernel_launch(void* const* d_in, const int* in_sizes, int n_in,
                              void* d_out, int out_size) {
    const float* key   = (const float*)d_in[0];
    const float* value = (const float*)d_in[1];
    const float* query = (const float*)d_in[2];
    const void*  mask  = d_in[3];
    const float* qmask = (const float*)d_in[4];

    float* out      = (float*)d_out;
    float* out_res  = out;                          // [B, T, D] first (tuple order)
    float* out_attn = out + (size_t)BB * TT * DD;   // [B, T, T] second

    prep_kernel<<<6145, 512>>>(query, key, value, (const unsigned char*)mask);

    cudaFuncSetAttribute(mh_attn_mma7_kernel,
                         cudaFuncAttributeMaxDynamicSharedMemorySize, SM_TOTAL);
    dim3 grid(BB * (TT / QT));   // 2048 CTAs
    mh_attn_mma7_kernel<<<grid, NTHREADS, SM_TOTAL>>>(mask, qmask, out_res, out_attn);
}